// round 1
// baseline (speedup 1.0000x reference)
#include <cuda_runtime.h>
#include <math.h>

#define S_LEN 2048
#define BATCH 2
#define HID   4096
#define NH    32
#define NKV   8
#define HD    128
#define WIN   1024
#define QDIM  (NH*HD)     // 4096
#define KVDIM (NKV*HD)    // 1024
#define MROWS (BATCH*S_LEN) // 4096

// Scratch buffers (device globals per harness allocation rules)
__device__ float g_Q[(size_t)MROWS*QDIM];
__device__ float g_K[(size_t)MROWS*KVDIM];
__device__ float g_V[(size_t)MROWS*KVDIM];
__device__ float g_AO[(size_t)MROWS*QDIM];

typedef unsigned long long ull;

__device__ __forceinline__ ull pk(float x, float y) {
    ull r; asm("mov.b64 %0,{%1,%2};" : "=l"(r) : "f"(x), "f"(y)); return r;
}
__device__ __forceinline__ float2 up(ull v) {
    float2 r; asm("mov.b64 {%0,%1},%2;" : "=f"(r.x), "=f"(r.y) : "l"(v)); return r;
}
__device__ __forceinline__ void fma2(ull &acc, ull a, ull b) {
    asm("fma.rn.f32x2 %0,%1,%2,%0;" : "+l"(acc) : "l"(a), "l"(b));
}
__device__ __forceinline__ ull mul2(ull a, ull b) {
    ull r; asm("mul.rn.f32x2 %0,%1,%2;" : "=l"(r) : "l"(a), "l"(b)); return r;
}

// ---------------------------------------------------------------------------
// NT SGEMM: C[m][n] = sum_k A[m*K+k] * B[n*K+k]
// 128x128 tile, BK=16, 256 threads, 8x8 microtile, packed f32x2 FMA.
// M,N multiples of 128; K multiple of 16.
// ---------------------------------------------------------------------------
__global__ void __launch_bounds__(256) sgemm_nt(
    const float* __restrict__ A, const float* __restrict__ B,
    float* __restrict__ C, int M, int N, int K)
{
    __shared__ __align__(16) float As[16][132];
    __shared__ __align__(16) float Bs[16][132];

    const int tid = threadIdx.x;
    const int tm  = tid >> 4;        // 0..15
    const int tn  = tid & 15;        // 0..15
    const int m0  = blockIdx.y * 128;
    const int n0  = blockIdx.x * 128;
    const int lr  = tid >> 2;        // 0..63
    const int lc  = (tid & 3) << 2;  // 0,4,8,12

    ull acc[8][4];
    #pragma unroll
    for (int i = 0; i < 8; ++i)
        #pragma unroll
        for (int j = 0; j < 4; ++j) acc[i][j] = 0ULL;

    for (int kt = 0; kt < K; kt += 16) {
        #pragma unroll
        for (int h = 0; h < 2; ++h) {
            int row = lr + h * 64;
            float4 a4 = *(const float4*)&A[(size_t)(m0 + row) * K + kt + lc];
            As[lc+0][row] = a4.x; As[lc+1][row] = a4.y;
            As[lc+2][row] = a4.z; As[lc+3][row] = a4.w;
            float4 b4 = *(const float4*)&B[(size_t)(n0 + row) * K + kt + lc];
            Bs[lc+0][row] = b4.x; Bs[lc+1][row] = b4.y;
            Bs[lc+2][row] = b4.z; Bs[lc+3][row] = b4.w;
        }
        __syncthreads();

        #pragma unroll
        for (int kk = 0; kk < 16; ++kk) {
            float4 a0 = *(const float4*)&As[kk][tm*8];
            float4 a1 = *(const float4*)&As[kk][tm*8+4];
            ulonglong2 b0 = *(const ulonglong2*)&Bs[kk][tn*8];
            ulonglong2 b1 = *(const ulonglong2*)&Bs[kk][tn*8+4];
            float av[8] = {a0.x,a0.y,a0.z,a0.w,a1.x,a1.y,a1.z,a1.w};
            #pragma unroll
            for (int i = 0; i < 8; ++i) {
                ull ap = pk(av[i], av[i]);
                fma2(acc[i][0], ap, b0.x);
                fma2(acc[i][1], ap, b0.y);
                fma2(acc[i][2], ap, b1.x);
                fma2(acc[i][3], ap, b1.y);
            }
        }
        __syncthreads();
    }

    #pragma unroll
    for (int i = 0; i < 8; ++i) {
        size_t row = (size_t)(m0 + tm*8 + i) * N + n0 + tn*8;
        *(float2*)&C[row + 0] = up(acc[i][0]);
        *(float2*)&C[row + 2] = up(acc[i][1]);
        *(float2*)&C[row + 4] = up(acc[i][2]);
        *(float2*)&C[row + 6] = up(acc[i][3]);
    }
}

// ---------------------------------------------------------------------------
// RoPE: buf layout [MROWS][nheads*128]. One thread per (row, head, pair i).
// ---------------------------------------------------------------------------
__global__ void rope_kernel(float* __restrict__ buf, int nheads)
{
    int idx = blockIdx.x * blockDim.x + threadIdx.x;
    int i   = idx & 63;
    int t   = idx >> 6;
    int h   = t % nheads;
    int row = t / nheads;          // b*S + s
    int s   = row & (S_LEN - 1);

    float inv = powf(10000.0f, -(float)i * (1.0f / 64.0f));
    float ang = (float)s * inv;
    float sn, cs;
    sincosf(ang, &sn, &cs);

    float* p = buf + (size_t)row * (nheads * HD) + h * HD;
    float x1 = p[i], x2 = p[i + 64];
    p[i]      = x1 * cs - x2 * sn;
    p[i + 64] = x2 * cs + x1 * sn;
}

// ---------------------------------------------------------------------------
// Flash attention with sliding window (causal, W=1024), GQA (4 q-heads per kv).
// Block: (q-tile of 64, head, batch). 256 threads, 4x4 score microtile,
// online softmax, 4x8 output microtile. f32x2 packed FMA throughout.
// ---------------------------------------------------------------------------
__global__ void __launch_bounds__(256) attn_kernel(
    const float* __restrict__ Qg, const float* __restrict__ Kg,
    const float* __restrict__ Vg, float* __restrict__ Og)
{
    extern __shared__ float smx[];
    float* Qs = smx;                 // [64][128]
    float* Ks = smx + 64*128;        // [128][66] transposed (d-major)
    float* Vs = Ks + 128*66;         // [64][128]
    float* Ps = Vs + 64*128;         // [64][64]

    const int tid = threadIdx.x;
    const int tm  = tid >> 4;        // 0..15 -> 4 query rows
    const int tn  = tid & 15;        // 0..15
    const int qb  = blockIdx.x;
    const int h   = blockIdx.y;
    const int b   = blockIdx.z;
    const int q0  = qb * 64;
    const int kvh = h >> 2;
    const float SC = 0.08838834764831845f;  // 1/sqrt(128)

    // Load Q tile
    #pragma unroll
    for (int it = 0; it < 8; ++it) {
        int idx = tid + it * 256;
        int r = idx >> 5;
        int d = (idx & 31) << 2;
        *(float4*)&Qs[r*128 + d] =
            *(const float4*)&Qg[(size_t)(b*S_LEN + q0 + r)*QDIM + h*HD + d];
    }

    ull o2[4][4];
    #pragma unroll
    for (int r = 0; r < 4; ++r)
        #pragma unroll
        for (int j = 0; j < 4; ++j) o2[r][j] = 0ULL;
    float mrow[4] = {-1e30f, -1e30f, -1e30f, -1e30f};
    float lrow[4] = {0.f, 0.f, 0.f, 0.f};

    const int lo  = (q0 > (WIN - 1)) ? (q0 - (WIN - 1)) : 0;
    const int kt0 = lo >> 6;

    for (int kt = kt0; kt <= qb; ++kt) {
        const int kbase = kt << 6;

        // Load K (transposed) and V tiles
        #pragma unroll
        for (int it = 0; it < 8; ++it) {
            int idx = tid + it * 256;
            int r = idx >> 5;
            int d = (idx & 31) << 2;
            size_t goff = (size_t)(b*S_LEN + kbase + r)*KVDIM + kvh*HD + d;
            float4 kv = *(const float4*)&Kg[goff];
            Ks[(d+0)*66 + r] = kv.x;
            Ks[(d+1)*66 + r] = kv.y;
            Ks[(d+2)*66 + r] = kv.z;
            Ks[(d+3)*66 + r] = kv.w;
            *(float4*)&Vs[r*128 + d] = *(const float4*)&Vg[goff];
        }
        __syncthreads();

        // S = Q K^T  (4 rows x 4 cols per thread, f32x2 along key dim)
        ull s2[4][2];
        #pragma unroll
        for (int r = 0; r < 4; ++r) { s2[r][0] = 0ULL; s2[r][1] = 0ULL; }

        #pragma unroll 4
        for (int d = 0; d < 128; d += 2) {
            float2 qr0 = *(const float2*)&Qs[(tm*4+0)*128 + d];
            float2 qr1 = *(const float2*)&Qs[(tm*4+1)*128 + d];
            float2 qr2 = *(const float2*)&Qs[(tm*4+2)*128 + d];
            float2 qr3 = *(const float2*)&Qs[(tm*4+3)*128 + d];
            ull k00 = *(const ull*)&Ks[d*66 + tn*4];
            ull k01 = *(const ull*)&Ks[d*66 + tn*4 + 2];
            ull k10 = *(const ull*)&Ks[(d+1)*66 + tn*4];
            ull k11 = *(const ull*)&Ks[(d+1)*66 + tn*4 + 2];
            fma2(s2[0][0], pk(qr0.x,qr0.x), k00); fma2(s2[0][1], pk(qr0.x,qr0.x), k01);
            fma2(s2[0][0], pk(qr0.y,qr0.y), k10); fma2(s2[0][1], pk(qr0.y,qr0.y), k11);
            fma2(s2[1][0], pk(qr1.x,qr1.x), k00); fma2(s2[1][1], pk(qr1.x,qr1.x), k01);
            fma2(s2[1][0], pk(qr1.y,qr1.y), k10); fma2(s2[1][1], pk(qr1.y,qr1.y), k11);
            fma2(s2[2][0], pk(qr2.x,qr2.x), k00); fma2(s2[2][1], pk(qr2.x,qr2.x), k01);
            fma2(s2[2][0], pk(qr2.y,qr2.y), k10); fma2(s2[2][1], pk(qr2.y,qr2.y), k11);
            fma2(s2[3][0], pk(qr3.x,qr3.x), k00); fma2(s2[3][1], pk(qr3.x,qr3.x), k01);
            fma2(s2[3][0], pk(qr3.y,qr3.y), k10); fma2(s2[3][1], pk(qr3.y,qr3.y), k11);
        }

        // Unpack, scale, mask, online softmax
        float sv[4][4];
        #pragma unroll
        for (int r = 0; r < 4; ++r) {
            float2 t0 = up(s2[r][0]);
            float2 t1 = up(s2[r][1]);
            sv[r][0] = t0.x * SC; sv[r][1] = t0.y * SC;
            sv[r][2] = t1.x * SC; sv[r][3] = t1.y * SC;
        }

        #pragma unroll
        for (int r = 0; r < 4; ++r) {
            const int qi = q0 + tm*4 + r;
            bool ok[4];
            float rm = -1e30f;
            #pragma unroll
            for (int c = 0; c < 4; ++c) {
                int kj = kbase + tn*4 + c;
                ok[c] = (kj <= qi) && ((qi - kj) < WIN);
                if (!ok[c]) sv[r][c] = -1e30f;
                rm = fmaxf(rm, sv[r][c]);
            }
            rm = fmaxf(rm, __shfl_xor_sync(0xffffffffu, rm, 1));
            rm = fmaxf(rm, __shfl_xor_sync(0xffffffffu, rm, 2));
            rm = fmaxf(rm, __shfl_xor_sync(0xffffffffu, rm, 4));
            rm = fmaxf(rm, __shfl_xor_sync(0xffffffffu, rm, 8));
            float mn = fmaxf(mrow[r], rm);

            float p[4], rs = 0.f;
            #pragma unroll
            for (int c = 0; c < 4; ++c) {
                p[c] = ok[c] ? __expf(sv[r][c] - mn) : 0.f;
                rs += p[c];
            }
            rs += __shfl_xor_sync(0xffffffffu, rs, 1);
            rs += __shfl_xor_sync(0xffffffffu, rs, 2);
            rs += __shfl_xor_sync(0xffffffffu, rs, 4);
            rs += __shfl_xor_sync(0xffffffffu, rs, 8);

            float scl = __expf(mrow[r] - mn);
            lrow[r] = lrow[r] * scl + rs;
            mrow[r] = mn;

            ull sp = pk(scl, scl);
            #pragma unroll
            for (int j = 0; j < 4; ++j) o2[r][j] = mul2(o2[r][j], sp);

            #pragma unroll
            for (int c = 0; c < 4; ++c)
                Ps[(tm*4+r)*64 + tn*4 + c] = p[c];
        }
        __syncthreads();

        // O += P @ V   (4 rows x 8 cols per thread)
        #pragma unroll 4
        for (int k = 0; k < 64; ++k) {
            ulonglong2 v0 = *(const ulonglong2*)&Vs[k*128 + tn*8];
            ulonglong2 v1 = *(const ulonglong2*)&Vs[k*128 + tn*8 + 4];
            #pragma unroll
            for (int r = 0; r < 4; ++r) {
                float pv = Ps[(tm*4+r)*64 + k];
                ull pp = pk(pv, pv);
                fma2(o2[r][0], pp, v0.x);
                fma2(o2[r][1], pp, v0.y);
                fma2(o2[r][2], pp, v1.x);
                fma2(o2[r][3], pp, v1.y);
            }
        }
        __syncthreads();
    }

    // Epilogue: O /= l, write out
    #pragma unroll
    for (int r = 0; r < 4; ++r) {
        float inv = 1.0f / lrow[r];
        ull ip = pk(inv, inv);
        float* orow = &Og[(size_t)(b*S_LEN + q0 + tm*4 + r)*QDIM + h*HD + tn*8];
        *(float2*)&orow[0] = up(mul2(o2[r][0], ip));
        *(float2*)&orow[2] = up(mul2(o2[r][1], ip));
        *(float2*)&orow[4] = up(mul2(o2[r][2], ip));
        *(float2*)&orow[6] = up(mul2(o2[r][3], ip));
    }
}

// ---------------------------------------------------------------------------
extern "C" void kernel_launch(void* const* d_in, const int* in_sizes, int n_in,
                              void* d_out, int out_size)
{
    const float* X  = (const float*)d_in[0];
    const float* Wq = (const float*)d_in[1];
    const float* Wk = (const float*)d_in[2];
    const float* Wv = (const float*)d_in[3];
    const float* Wo = (const float*)d_in[4];
    float* out = (float*)d_out;

    float *q, *k, *v, *ao;
    cudaGetSymbolAddress((void**)&q,  g_Q);
    cudaGetSymbolAddress((void**)&k,  g_K);
    cudaGetSymbolAddress((void**)&v,  g_V);
    cudaGetSymbolAddress((void**)&ao, g_AO);

    // Projections: x @ W^T  (NT gemms)
    sgemm_nt<<<dim3(QDIM/128,  MROWS/128), 256>>>(X, Wq, q, MROWS, QDIM,  HID);
    sgemm_nt<<<dim3(KVDIM/128, MROWS/128), 256>>>(X, Wk, k, MROWS, KVDIM, HID);
    sgemm_nt<<<dim3(KVDIM/128, MROWS/128), 256>>>(X, Wv, v, MROWS, KVDIM, HID);

    // RoPE on Q and K
    rope_kernel<<<(MROWS*NH*64)/256,  256>>>(q, NH);
    rope_kernel<<<(MROWS*NKV*64)/256, 256>>>(k, NKV);

    // Sliding-window flash attention
    const int smem_bytes = (64*128 + 128*66 + 64*128 + 64*64) * 4;  // 115712
    cudaFuncSetAttribute(attn_kernel,
                         cudaFuncAttributeMaxDynamicSharedMemorySize, smem_bytes);
    attn_kernel<<<dim3(S_LEN/64, NH, BATCH), 256, smem_bytes>>>(q, k, v, ao);

    // Output projection
    sgemm_nt<<<dim3(QDIM/128, MROWS/128), 256>>>(ao, Wo, out, MROWS, QDIM, HID);
}